// round 3
// baseline (speedup 1.0000x reference)
#include <cuda_runtime.h>
#include <cstdint>

#define T_LEN   512
#define BATCH   2048
#define NB      8            // batches per block
#define HID     64
#define NGATE   256
#define THREADS 256          // one thread per gate row

typedef unsigned long long ull;

__device__ __forceinline__ uint32_t smem_u32(const void* p) {
    uint32_t a;
    asm("{ .reg .u64 t; cvta.to.shared.u64 t, %1; cvt.u32.u64 %0, t; }"
        : "=r"(a) : "l"(p));
    return a;
}
// 16B shared load straight into two b64 regs (no pack MOVs)
__device__ __forceinline__ void lds_v2u64(ull& a, ull& b, uint32_t addr) {
    asm volatile("ld.shared.v2.u64 {%0, %1}, [%2];"
                 : "=l"(a), "=l"(b) : "r"(addr));
}
__device__ __forceinline__ ull pack2(float x, float y) {
    ull r; asm("mov.b64 %0, {%1, %2};" : "=l"(r) : "f"(x), "f"(y)); return r;
}
__device__ __forceinline__ void unpack2(ull v, float& x, float& y) {
    asm("mov.b64 {%0, %1}, %2;" : "=f"(x), "=f"(y) : "l"(v));
}
// Packed f32x2 FMA (sm_10x FFMA2) — IEEE fp32 per lane, 2x FFMA throughput.
__device__ __forceinline__ ull fma2(ull a, ull b, ull c) {
    ull d; asm("fma.rn.f32x2 %0, %1, %2, %3;" : "=l"(d) : "l"(a), "l"(b), "l"(c));
    return d;
}
__device__ __forceinline__ float sigm(float x) {
    float e = __expf(-x);
    return __fdividef(1.0f, 1.0f + e);
}
__device__ __forceinline__ float tanh_fast(float x) {
    float e = __expf(-2.0f * x);
    return __fdividef(2.0f, 1.0f + e) - 1.0f;
}

__global__ __launch_bounds__(THREADS, 2)
void lstm_kernel(const float* __restrict__ x,
                 const float* __restrict__ w_ih,
                 const float* __restrict__ w_hh,
                 const float* __restrict__ b_ih,
                 const float* __restrict__ b_hh,
                 const float* __restrict__ w_fc,
                 const float* __restrict__ b_fc,
                 float* __restrict__ out)
{
    __shared__ __align__(16) float h_sh[NB][HID];       // 2 KB (single buffer; 2 bars/step)
    __shared__ __align__(16) float gbuf[NB][NGATE];     // 8 KB gate transpose
    __shared__ __align__(16) float x_sh[NB][64];        // 2 KB input chunk (64 steps)
    __shared__ float obuf[8][2];                        // per-warp output partials

    const int tid = threadIdx.x;
    const int b0  = blockIdx.x * NB;

    // ---- thread r = tid owns gate row tid: weights in registers ----
    const float wih  = w_ih[tid];                       // I == 1
    const float bias = b_ih[tid] + b_hh[tid];
    ull wreg[32];
    {
        const float* wrow = w_hh + (size_t)tid * HID;
        #pragma unroll
        for (int j = 0; j < 32; ++j)
            wreg[j] = *(const ull*)(wrow + 2 * j);
    }

    // ---- update-phase identity: units (bb,u) and (bb+4,u) ----
    const int bb = tid >> 6;                            // 0..3
    const int u  = tid & 63;
    const float wfcu = w_fc[u];
    const float bfc  = b_fc[0];

    // init h = 0, stage x chunk 0 (steps 0..63)
    ((float*)h_sh)[tid]       = 0.0f;
    ((float*)h_sh)[tid + 256] = 0.0f;
    {
        int b = tid >> 6, t2 = tid & 63;
        x_sh[b][t2] = x[(size_t)(b0 + b) * T_LEN + t2];
        int idx = tid + 256; b = idx >> 6; t2 = idx & 63;
        x_sh[b][t2] = x[(size_t)(b0 + b) * T_LEN + t2];
    }

    const uint32_t hbase = smem_u32(&h_sh[0][0]);
    float c_a = 0.0f, c_b = 0.0f;
    __syncthreads();

    for (int t = 0; t < T_LEN; ++t) {
        const int tt = t & 63;

        // ---- phase A: gates[b][r] = x*wih + bias + h[b]·w_row (all in regs) ----
        ull acc[NB];
        #pragma unroll
        for (int b = 0; b < NB; ++b) {
            float xv = x_sh[b][tt];                     // broadcast LDS
            acc[b] = pack2(fmaf(xv, wih, bias), 0.0f);
        }
        #pragma unroll 4
        for (int k4 = 0; k4 < 16; ++k4) {
            #pragma unroll
            for (int b = 0; b < NB; ++b) {
                ull hlo, hhi;                           // broadcast 16B load
                lds_v2u64(hlo, hhi, hbase + (uint32_t)((b * HID + k4 * 4) * 4));
                acc[b] = fma2(hlo, wreg[2 * k4],     acc[b]);
                acc[b] = fma2(hhi, wreg[2 * k4 + 1], acc[b]);
            }
        }
        #pragma unroll
        for (int b = 0; b < NB; ++b) {
            float lo, hi; unpack2(acc[b], lo, hi);
            gbuf[b][tid] = lo + hi;
        }
        __syncthreads();                                // bar1: gates visible

        // ---- update phase: PyTorch gate order i,f,g,o ----
        float gi_a = gbuf[bb][u],           gf_a = gbuf[bb][u + 64];
        float gg_a = gbuf[bb][u + 128],     go_a = gbuf[bb][u + 192];
        float gi_b = gbuf[bb + 4][u],       gf_b = gbuf[bb + 4][u + 64];
        float gg_b = gbuf[bb + 4][u + 128], go_b = gbuf[bb + 4][u + 192];

        float ia = sigm(gi_a), fa = sigm(gf_a), ga = tanh_fast(gg_a), oa = sigm(go_a);
        c_a = fmaf(fa, c_a, ia * ga);
        float ha = oa * tanh_fast(c_a);

        float ib = sigm(gi_b), fb = sigm(gf_b), gb = tanh_fast(gg_b), ob = sigm(go_b);
        c_b = fmaf(fb, c_b, ib * gb);
        float hb = ob * tanh_fast(c_b);

        h_sh[bb][u]     = ha;                           // safe: bar1 separates from reads
        h_sh[bb + 4][u] = hb;

        // ---- output head partials: out[b][t] = h·w_fc + b_fc ----
        float pa = ha * wfcu, pb = hb * wfcu;
        #pragma unroll
        for (int off = 16; off > 0; off >>= 1) {
            pa += __shfl_xor_sync(0xffffffffu, pa, off);
            pb += __shfl_xor_sync(0xffffffffu, pb, off);
        }
        const int w = tid >> 5;                         // bb = w>>1, half = w&1
        if ((tid & 31) == 0) { obuf[w][0] = pa; obuf[w][1] = pb; }

        // ---- stage next 64-step x chunk (hidden under update phase) ----
        if (tt == 63 && t + 1 < T_LEN) {
            int b = tid >> 6, t2 = tid & 63;
            x_sh[b][t2] = x[(size_t)(b0 + b) * T_LEN + (t + 1) + t2];
            int idx = tid + 256; b = idx >> 6; t2 = idx & 63;
            x_sh[b][t2] = x[(size_t)(b0 + b) * T_LEN + (t + 1) + t2];
        }
        __syncthreads();                                // bar2: h + obuf visible

        if (tid < 8) {
            float v = (tid < 4)
                ? obuf[2 * tid][0]       + obuf[2 * tid + 1][0]
                : obuf[2 * (tid - 4)][1] + obuf[2 * (tid - 4) + 1][1];
            out[(size_t)(b0 + tid) * T_LEN + t] = v + bfc;
        }
    }
}

extern "C" void kernel_launch(void* const* d_in, const int* in_sizes, int n_in,
                              void* d_out, int out_size)
{
    const float* x    = (const float*)d_in[0];
    const float* w_ih = (const float*)d_in[1];
    const float* w_hh = (const float*)d_in[2];
    const float* b_ih = (const float*)d_in[3];
    const float* b_hh = (const float*)d_in[4];
    const float* w_fc = (const float*)d_in[5];
    const float* b_fc = (const float*)d_in[6];
    float* out = (float*)d_out;

    lstm_kernel<<<BATCH / NB, THREADS>>>(x, w_ih, w_hh, b_ih, b_hh,
                                         w_fc, b_fc, out);
}

// round 4
// speedup vs baseline: 1.4088x; 1.4088x over previous
#include <cuda_runtime.h>
#include <cstdint>

#define T_LEN   512
#define BATCH   2048
#define NB      16
#define HID     64
#define NGATE   256
#define THREADS 256          // 8 warps: warp = 32-row slice x 16 batches
#define WP      68           // w_sh row stride (floats): bank 4*rg, conflict-free
#define HP      68           // h_sh row stride: bank 4*b -> 4 distinct for b=bl+4i
#define GP      264          // gbuf row stride: bank 8*b + r -> 32 distinct on STS
#define XP      65           // x_sh row stride

typedef unsigned long long ull;

__device__ __forceinline__ uint32_t smem_u32(const void* p) {
    uint32_t a;
    asm("{ .reg .u64 t; cvta.to.shared.u64 t, %1; cvt.u32.u64 %0, t; }"
        : "=r"(a) : "l"(p));
    return a;
}
// 16B shared load straight into two b64 regs (no pack MOVs)
__device__ __forceinline__ void lds_v2u64(ull& a, ull& b, uint32_t addr) {
    asm volatile("ld.shared.v2.u64 {%0, %1}, [%2];"
                 : "=l"(a), "=l"(b) : "r"(addr));
}
__device__ __forceinline__ ull pack2(float x, float y) {
    ull r; asm("mov.b64 %0, {%1, %2};" : "=l"(r) : "f"(x), "f"(y)); return r;
}
__device__ __forceinline__ void unpack2(ull v, float& x, float& y) {
    asm("mov.b64 {%0, %1}, %2;" : "=f"(x), "=f"(y) : "l"(v));
}
// Packed f32x2 FMA (sm_10x FFMA2) — IEEE fp32 per lane, 2x FFMA throughput.
__device__ __forceinline__ ull fma2(ull a, ull b, ull c) {
    ull d; asm("fma.rn.f32x2 %0, %1, %2, %3;" : "=l"(d) : "l"(a), "l"(b), "l"(c));
    return d;
}
__device__ __forceinline__ float sigm(float x) {
    float e = __expf(-x);
    return __fdividef(1.0f, 1.0f + e);
}
__device__ __forceinline__ float tanh_fast(float x) {
    float e = __expf(-2.0f * x);
    return __fdividef(2.0f, 1.0f + e) - 1.0f;
}

__global__ __launch_bounds__(THREADS, 1)
void lstm_kernel(const float* __restrict__ x,
                 const float* __restrict__ w_ih,
                 const float* __restrict__ w_hh,
                 const float* __restrict__ b_ih,
                 const float* __restrict__ b_hh,
                 const float* __restrict__ w_fc,
                 const float* __restrict__ b_fc,
                 float* __restrict__ out)
{
    extern __shared__ float smem[];
    float* w_sh = smem;                       // [NGATE][WP]  69632 B
    float* h_sh = w_sh + NGATE * WP;          // [NB][HP]      4352 B
    float* gbuf = h_sh + NB * HP;             // [NB][GP]     16896 B
    float* x_sh = gbuf + NB * GP;             // [NB][XP]      4160 B

    const int tid  = threadIdx.x;
    const int lane = tid & 31;
    const int warp = tid >> 5;                // 0..7: row slice warp*32..+31
    const int rg   = lane & 7;                // row offset within 8-group
    const int bl   = lane >> 3;               // batch lane group 0..3
    const int b0   = blockIdx.x * NB;

    // ---- stage w_hh into padded shared; zero h; stage x chunk 0 ----
    for (int idx = tid; idx < NGATE * HID; idx += THREADS) {
        int r = idx >> 6, k = idx & 63;
        w_sh[r * WP + k] = w_hh[idx];
    }
    for (int idx = tid; idx < NB * HP; idx += THREADS) h_sh[idx] = 0.0f;
    for (int idx = tid; idx < NB * HID; idx += THREADS) {
        int b = idx >> 6, t2 = idx & 63;
        x_sh[b * XP + t2] = x[(size_t)(b0 + b) * T_LEN + t2];
    }

    // ---- matvec identity: rows r_j = warp*32+rg+8j, batches b_i = bl+4i ----
    float wih[4], bias[4];
    uint32_t waddr[4], haddr[4];
    const uint32_t wbase = smem_u32(w_sh);
    const uint32_t hbase = smem_u32(h_sh);
    #pragma unroll
    for (int j = 0; j < 4; ++j) {
        int r = warp * 32 + rg + 8 * j;
        wih[j]   = w_ih[r];                   // I == 1
        bias[j]  = b_ih[r] + b_hh[r];
        waddr[j] = wbase + (uint32_t)(r * WP) * 4u;
    }
    #pragma unroll
    for (int i = 0; i < 4; ++i)
        haddr[i] = hbase + (uint32_t)((bl + 4 * i) * HP) * 4u;

    // ---- update identity: batch ub = tid>>4, units uu+16m ----
    const int ub = tid >> 4;
    const int uu = tid & 15;
    float wfc[4], c[4];
    #pragma unroll
    for (int m = 0; m < 4; ++m) { wfc[m] = w_fc[uu + 16 * m]; c[m] = 0.0f; }
    const float bfc = b_fc[0];

    __syncthreads();

    for (int t = 0; t < T_LEN; ++t) {
        const int tt = t & 63;

        // ---- matvec phase: acc[j][i] = gates(row j, batch i), f32x2 over k ----
        ull acc[4][4];
        #pragma unroll
        for (int i = 0; i < 4; ++i) {
            float xv = x_sh[(bl + 4 * i) * XP + tt];
            #pragma unroll
            for (int j = 0; j < 4; ++j)
                acc[j][i] = pack2(fmaf(xv, wih[j], bias[j]), 0.0f);
        }

        ull chlo[4], chhi[4], cwlo[4], cwhi[4];
        #pragma unroll
        for (int i = 0; i < 4; ++i) lds_v2u64(chlo[i], chhi[i], haddr[i]);
        #pragma unroll
        for (int j = 0; j < 4; ++j) lds_v2u64(cwlo[j], cwhi[j], waddr[j]);

        #pragma unroll
        for (int kc = 0; kc < 16; ++kc) {
            ull nhlo[4], nhhi[4], nwlo[4], nwhi[4];
            if (kc < 15) {                      // prefetch next chunk (compile-time)
                const uint32_t off = 16u * (uint32_t)(kc + 1);
                #pragma unroll
                for (int i = 0; i < 4; ++i) lds_v2u64(nhlo[i], nhhi[i], haddr[i] + off);
                #pragma unroll
                for (int j = 0; j < 4; ++j) lds_v2u64(nwlo[j], nwhi[j], waddr[j] + off);
            }
            #pragma unroll
            for (int j = 0; j < 4; ++j)
                #pragma unroll
                for (int i = 0; i < 4; ++i) {
                    acc[j][i] = fma2(chlo[i], cwlo[j], acc[j][i]);
                    acc[j][i] = fma2(chhi[i], cwhi[j], acc[j][i]);
                }
            if (kc < 15) {
                #pragma unroll
                for (int i = 0; i < 4; ++i) { chlo[i] = nhlo[i]; chhi[i] = nhhi[i]; }
                #pragma unroll
                for (int j = 0; j < 4; ++j) { cwlo[j] = nwlo[j]; cwhi[j] = nwhi[j]; }
            }
        }

        // gates -> gbuf (conflict-free: bank = 8*bl + rg + 8j, all 32 distinct)
        #pragma unroll
        for (int j = 0; j < 4; ++j) {
            int r = warp * 32 + rg + 8 * j;
            #pragma unroll
            for (int i = 0; i < 4; ++i) {
                float lo, hi; unpack2(acc[j][i], lo, hi);
                gbuf[(bl + 4 * i) * GP + r] = lo + hi;
            }
        }
        __syncthreads();                        // bar1: gates visible

        // ---- update phase (PyTorch gate order i,f,g,o) ----
        float po = 0.0f;
        #pragma unroll
        for (int m = 0; m < 4; ++m) {
            const int u = uu + 16 * m;
            float gi = gbuf[ub * GP + u];
            float gf = gbuf[ub * GP + 64 + u];
            float gg = gbuf[ub * GP + 128 + u];
            float go = gbuf[ub * GP + 192 + u];
            float iv = sigm(gi), fv = sigm(gf);
            float gv = tanh_fast(gg), ov = sigm(go);
            c[m] = fmaf(fv, c[m], iv * gv);
            float hv = ov * tanh_fast(c[m]);
            h_sh[ub * HP + u] = hv;
            po = fmaf(hv, wfc[m], po);
        }
        // reduce over the 16 unit-threads of batch ub (aligned 16-lane groups)
        po += __shfl_xor_sync(0xffffffffu, po, 8);
        po += __shfl_xor_sync(0xffffffffu, po, 4);
        po += __shfl_xor_sync(0xffffffffu, po, 2);
        po += __shfl_xor_sync(0xffffffffu, po, 1);
        if (uu == 0) out[(size_t)(b0 + ub) * T_LEN + t] = po + bfc;

        // stage next x chunk while update finishes (matvec reads of chunk done)
        if (tt == 63 && t + 1 < T_LEN) {
            #pragma unroll
            for (int q = 0; q < 4; ++q) {
                int idx = tid + 256 * q;
                int b = idx >> 6, t2 = idx & 63;
                x_sh[b * XP + t2] = x[(size_t)(b0 + b) * T_LEN + (t + 1) + t2];
            }
        }
        __syncthreads();                        // bar2: h + x visible for next step
    }
}

extern "C" void kernel_launch(void* const* d_in, const int* in_sizes, int n_in,
                              void* d_out, int out_size)
{
    const float* x    = (const float*)d_in[0];
    const float* w_ih = (const float*)d_in[1];
    const float* w_hh = (const float*)d_in[2];
    const float* b_ih = (const float*)d_in[3];
    const float* b_hh = (const float*)d_in[4];
    const float* w_fc = (const float*)d_in[5];
    const float* b_fc = (const float*)d_in[6];
    float* out = (float*)d_out;

    size_t smem = (size_t)(NGATE * WP + NB * HP + NB * GP + NB * XP) * sizeof(float);
    cudaFuncSetAttribute(lstm_kernel,
                         cudaFuncAttributeMaxDynamicSharedMemorySize, (int)smem);
    lstm_kernel<<<BATCH / NB, THREADS, smem>>>(x, w_ih, w_hh, b_ih, b_hh,
                                               w_fc, b_fc, out);
}